// round 1
// baseline (speedup 1.0000x reference)
#include <cuda_runtime.h>
#include <math.h>

// ---------------- problem constants ----------------
#define BB 2
#define LL 2048
#define HH 8
#define DD 64
#define KMAX 2
#define EE 32
#define LOGN 12
#define LEAF 4096
#define NDUSED 12          // depths 0..11 are the only ones referenced
#define DMODEL 512

// ---------------- device scratch (static, no allocs) ----------------
__device__ float g_tree[8192 * BB * HH * KMAX * DD];          // 64 MB
__device__ float g_qbase[BB * LL * DMODEL];                   // 8 MB
__device__ float g_qall[BB * LL * NDUSED * DMODEL];           // 100 MB  (b,l,s,h,d)
__device__ float g_ctx[BB * LL * DMODEL];                     // 8 MB

__device__ float4 g_gw[160][32];    // [i][lane] = {gl[lane][i], gl[lane+32][i], gr[lane][i], gr[lane+32][i]}
__device__ float2 g_skw[64][32];    // [i][lane] = {skip_w[lane][i], skip_w[lane+32][i]}
__device__ float  g_dv[13][32];
__device__ float  g_pr[13][8];
__device__ float  g_pi[13][8];
__device__ float  g_pq[13][2][64];
__device__ float  g_scale[13];
__device__ float  g_sigalpha;

// ---------------- helpers ----------------
__device__ __forceinline__ float wsum(float v) {
    v += __shfl_xor_sync(0xffffffffu, v, 16);
    v += __shfl_xor_sync(0xffffffffu, v, 8);
    v += __shfl_xor_sync(0xffffffffu, v, 4);
    v += __shfl_xor_sync(0xffffffffu, v, 2);
    v += __shfl_xor_sync(0xffffffffu, v, 1);
    return v;
}
__device__ __forceinline__ float sigf(float x) { return 1.0f / (1.0f + __expf(-x)); }

// ---------------- precompute small tables ----------------
__global__ void precompute_kernel(
    const float* __restrict__ glw, const float* __restrict__ grw,
    const float* __restrict__ pqb, const float* __restrict__ qow,
    const float* __restrict__ qob, const float* __restrict__ skw,
    const float* __restrict__ salpha, const float* __restrict__ wfreq,
    const float* __restrict__ wdamp, const float* __restrict__ wphase,
    const float* __restrict__ dtemp)
{
    int t = threadIdx.x;  // 256 threads

    // interleaved gate weights: glw/grw are (64,160) row-major
    for (int idx = t; idx < 160 * 32; idx += 256) {
        int i = idx >> 5, l = idx & 31;
        g_gw[i][l] = make_float4(glw[l * 160 + i], glw[(l + 32) * 160 + i],
                                 grw[l * 160 + i], grw[(l + 32) * 160 + i]);
    }
    // skip weights (64,64)
    for (int idx = t; idx < 64 * 32; idx += 256) {
        int i = idx >> 5, l = idx & 31;
        g_skw[i][l] = make_float2(skw[l * 64 + i], skw[(l + 32) * 64 + i]);
    }
    // depth embedding: dv[d][2i] = sin(d*inv_i), dv[d][2i+1] = cos(d*inv_i)
    for (int idx = t; idx < 13 * 32; idx += 256) {
        int d = idx >> 5, e = idx & 31;
        int i = e >> 1;
        float inv = expf(-(2.0f * (float)i) * logf(10000.0f) / 32.0f);
        float a = (float)d * inv;
        g_dv[d][e] = (e & 1) ? cosf(a) : sinf(a);
    }
    // wave rotation coeffs: pr/pi depend only on (h, depth)
    if (t < 13 * 8) {
        int d = t >> 3, h = t & 7;
        float sp = log1pf(expf(wdamp[h]));           // softplus
        float decay = expf(-sp);
        float ang = wfreq[h] + wphase[h] + (float)d * 0.78539816339744831f;
        g_pr[d][h] = decay * cosf(ang);
        g_pi[d][h] = decay * sinf(ang);
    }
    if (t < 13) {
        float sp = log1pf(expf(dtemp[t]));
        g_scale[t] = 1.0f / ((sp + 1e-6f) * 8.0f);   // 1/(softplus(temp)+1e-6)/sqrt(64)
    }
    if (t == 0) g_sigalpha = 1.0f / (1.0f + expf(-salpha[0]));

    __syncthreads();  // dv needed below

    // pq[d][k][j] = parent_query_base[k][j] + qob[k*64+j] + sum_e qow[(k*64+j)][e]*dv[d][e]
    for (int idx = t; idx < 13 * 128; idx += 256) {
        int d = idx >> 7, kj = idx & 127;
        float s = pqb[kj] + qob[kj];
        for (int e = 0; e < 32; e++) s += qow[kj * 32 + e] * g_dv[d][e];
        g_pq[d][kj >> 6][kj & 63] = s;
    }
}

// ---------------- generic fp32 GEMM: C = A(MxK) @ W(NxK)^T ----------------
// MODE: 0 -> plain C param; 1 -> scatter into tree leaves (v); 2 -> write g_qbase
// ASRC: 0 -> A param; 1 -> A = g_ctx
template <int MODE, int ASRC>
__global__ void gemm_kernel(const float* __restrict__ A, const float* __restrict__ W,
                            float* __restrict__ C, int M, int N, int K)
{
    __shared__ float As[16][132];
    __shared__ float Ws[16][68];
    const float* Ab = (ASRC == 0) ? A : g_ctx;
    int t = threadIdx.x;
    int tx = t & 15, ty = t >> 4;
    int m0 = blockIdx.x * 128, n0 = blockIdx.y * 64;

    float acc[8][4];
#pragma unroll
    for (int i = 0; i < 8; i++)
#pragma unroll
        for (int j = 0; j < 4; j++) acc[i][j] = 0.0f;

    for (int k0 = 0; k0 < K; k0 += 16) {
#pragma unroll
        for (int j = 0; j < 2; j++) {
            int q = t + 256 * j;
            int r = q >> 2, kq = q & 3;
            float4 v = *(const float4*)(Ab + (size_t)(m0 + r) * K + k0 + kq * 4);
            As[kq * 4 + 0][r] = v.x; As[kq * 4 + 1][r] = v.y;
            As[kq * 4 + 2][r] = v.z; As[kq * 4 + 3][r] = v.w;
        }
        {
            int n = t >> 2, kq = t & 3;
            float4 v = *(const float4*)(W + (size_t)(n0 + n) * K + k0 + kq * 4);
            Ws[kq * 4 + 0][n] = v.x; Ws[kq * 4 + 1][n] = v.y;
            Ws[kq * 4 + 2][n] = v.z; Ws[kq * 4 + 3][n] = v.w;
        }
        __syncthreads();
#pragma unroll
        for (int kk = 0; kk < 16; kk++) {
            float4 a0 = *(const float4*)&As[kk][ty * 8];
            float4 a1 = *(const float4*)&As[kk][ty * 8 + 4];
            float4 bv = *(const float4*)&Ws[kk][tx * 4];
            float av[8] = {a0.x, a0.y, a0.z, a0.w, a1.x, a1.y, a1.z, a1.w};
            float bw[4] = {bv.x, bv.y, bv.z, bv.w};
#pragma unroll
            for (int i = 0; i < 8; i++)
#pragma unroll
                for (int j = 0; j < 4; j++) acc[i][j] = fmaf(av[i], bw[j], acc[i][j]);
        }
        __syncthreads();
    }

    if (MODE == 0) {
#pragma unroll
        for (int i = 0; i < 8; i++) {
            float4 v = make_float4(acc[i][0], acc[i][1], acc[i][2], acc[i][3]);
            *(float4*)(C + (size_t)(m0 + ty * 8 + i) * N + n0 + tx * 4) = v;
        }
    } else if (MODE == 2) {
#pragma unroll
        for (int i = 0; i < 8; i++) {
            float4 v = make_float4(acc[i][0], acc[i][1], acc[i][2], acc[i][3]);
            *(float4*)(g_qbase + (size_t)(m0 + ty * 8 + i) * DMODEL + n0 + tx * 4) = v;
        }
    } else {  // leaf scatter: row m = b*L+l, col n = h*64+dd -> tree[4096+l][b][h][0][dd]
        int n = n0 + tx * 4;
        int hh = n >> 6, dd = n & 63;
#pragma unroll
        for (int i = 0; i < 8; i++) {
            int mm = m0 + ty * 8 + i;
            int bb = mm >> 11, ll = mm & 2047;
            float* p = g_tree + (size_t)((((LEAF + ll) * 2 + bb) * 8 + hh)) * 128 + dd;
            *(float4*)p = make_float4(acc[i][0], acc[i][1], acc[i][2], acc[i][3]);
        }
    }
}

// ---------------- q_all: per depth n, q_all[n] = q_base + q_base @ W[n]^T ----------------
// q_base viewed as (32768 x 64); output layout (b,l,n,h,d)
__global__ void qproj_kernel(const float* __restrict__ dpw)
{
    __shared__ float As[64][68];
    __shared__ float Ws[64][68];
    int t = threadIdx.x;
    int tx = t & 15, ty = t >> 4;
    int row0 = blockIdx.x * 64;

#pragma unroll
    for (int j = 0; j < 4; j++) {
        int q = t + 256 * j;
        int r = q >> 4, dq = q & 15;
        float4 v = *(const float4*)(g_qbase + (size_t)(row0 + r) * 64 + dq * 4);
        As[dq * 4 + 0][r] = v.x; As[dq * 4 + 1][r] = v.y;
        As[dq * 4 + 2][r] = v.z; As[dq * 4 + 3][r] = v.w;
    }

    for (int n = 0; n < NDUSED; n++) {
        __syncthreads();
        const float* W = dpw + (size_t)n * 4096;  // (o,d) row-major 64x64
#pragma unroll
        for (int j = 0; j < 4; j++) {
            int q = t + 256 * j;
            int o = q >> 4, dq = q & 15;
            float4 v = *(const float4*)(W + (size_t)o * 64 + dq * 4);
            Ws[dq * 4 + 0][o] = v.x; Ws[dq * 4 + 1][o] = v.y;
            Ws[dq * 4 + 2][o] = v.z; Ws[dq * 4 + 3][o] = v.w;
        }
        __syncthreads();

        float acc[4][4];
#pragma unroll
        for (int i = 0; i < 4; i++)
#pragma unroll
            for (int j = 0; j < 4; j++) acc[i][j] = 0.0f;

#pragma unroll 8
        for (int dd = 0; dd < 64; dd++) {
            float4 a = *(const float4*)&As[dd][ty * 4];
            float4 b = *(const float4*)&Ws[dd][tx * 4];
            float av[4] = {a.x, a.y, a.z, a.w};
            float bw[4] = {b.x, b.y, b.z, b.w};
#pragma unroll
            for (int i = 0; i < 4; i++)
#pragma unroll
                for (int j = 0; j < 4; j++) acc[i][j] = fmaf(av[i], bw[j], acc[i][j]);
        }
        // identity term
#pragma unroll
        for (int i = 0; i < 4; i++)
#pragma unroll
            for (int j = 0; j < 4; j++) acc[i][j] += As[tx * 4 + j][ty * 4 + i];
        // write
#pragma unroll
        for (int i = 0; i < 4; i++) {
            int rg = row0 + ty * 4 + i;
            int bl = rg >> 3, hh = rg & 7;
            float4 v = make_float4(acc[i][0], acc[i][1], acc[i][2], acc[i][3]);
            *(float4*)(g_qall + ((size_t)(bl * NDUSED + n) * 8 + hh) * 64 + tx * 4) = v;
        }
    }
}

// ---------------- tree merge, one warp per (node,b,h) ----------------
template <int KC>
__global__ void merge_kernel(int d, int lo,
                             const float* __restrict__ glb, const float* __restrict__ grb,
                             const float* __restrict__ ln_g, const float* __restrict__ ln_b)
{
    constexpr int NS = 2 * KC;
    __shared__ float s_gin[8][160];
    int warp = threadIdx.x >> 5;
    int lane = threadIdx.x & 31;
    int inst = blockIdx.x * 8 + warp;
    int total = lo * 16;
    if (inst >= total) return;
    int node = lo + (inst >> 4);
    int b = (inst >> 3) & 1;
    int h = inst & 7;

    const float* tl = g_tree + (size_t)(((2 * node) * 2 + b) * 8 + h) * 128;
    const float* tr = g_tree + (size_t)(((2 * node + 1) * 2 + b) * 8 + h) * 128;

    float pr = g_pr[d][h], pi = g_pi[d][h];
    float fla[KC], flb[KC], rta[KC], rtb[KC];
#pragma unroll
    for (int k = 0; k < KC; k++) {
        fla[k] = tl[k * 64 + lane];
        flb[k] = tl[k * 64 + lane + 32];
        float fr = tr[k * 64 + lane];
        float fi = tr[k * 64 + lane + 32];
        rta[k] = pr * fr - pi * fi;
        rtb[k] = pi * fr + pr * fi;
    }
    float lma, lmb, rma, rmb;
    if (KC == 2) {
        lma = 0.5f * (fla[0] + fla[1]); lmb = 0.5f * (flb[0] + flb[1]);
        rma = 0.5f * (rta[0] + rta[1]); rmb = 0.5f * (rtb[0] + rtb[1]);
    } else {
        lma = fla[0]; lmb = flb[0]; rma = rta[0]; rmb = rtb[0];
    }
    float* gin = s_gin[warp];
    gin[lane] = lma; gin[lane + 32] = lmb;
    gin[64 + lane] = rma; gin[96 + lane] = rmb;
    gin[128 + lane] = g_dv[d][lane];
    __syncwarp();

    float al0 = glb[lane], al1 = glb[lane + 32];
    float ar0 = grb[lane], ar1 = grb[lane + 32];
#pragma unroll 4
    for (int i = 0; i < 160; i++) {
        float4 w = g_gw[i][lane];
        float gi = gin[i];
        al0 = fmaf(w.x, gi, al0); al1 = fmaf(w.y, gi, al1);
        ar0 = fmaf(w.z, gi, ar0); ar1 = fmaf(w.w, gi, ar1);
    }
    float gla = sigf(al0), glv = sigf(al1), gra = sigf(ar0), grv = sigf(ar1);

    float bka[NS], bkb[NS];
#pragma unroll
    for (int k = 0; k < KC; k++) {
        bka[k] = fla[k] * gla;      bkb[k] = flb[k] * glv;
        bka[KC + k] = rta[k] * gra; bkb[KC + k] = rtb[k] * grv;
    }

    // skip = lm @ skip_w^T
    float ska = 0.0f, skb = 0.0f;
#pragma unroll 4
    for (int i = 0; i < 64; i++) {
        float2 w = g_skw[i][lane];
        float l = gin[i];
        ska = fmaf(w.x, l, ska);
        skb = fmaf(w.y, l, skb);
    }
    float sa = g_sigalpha;
    float gma = ln_g[lane], gmb = ln_g[lane + 32];
    float bta = ln_b[lane], btb = ln_b[lane + 32];
    size_t obase = (size_t)((node * 2 + b) * 8 + h) * 128;

#pragma unroll
    for (int q = 0; q < 2; q++) {
        float pqa = g_pq[d][q][lane], pqb = g_pq[d][q][lane + 32];
        float sc[NS];
#pragma unroll
        for (int s = 0; s < NS; s++) {
            float p = pqa * bka[s] + pqb * bkb[s];
            sc[s] = wsum(p) * 0.125f;
        }
        float mx = sc[0];
#pragma unroll
        for (int s = 1; s < NS; s++) mx = fmaxf(mx, sc[s]);
        float den = 0.0f;
#pragma unroll
        for (int s = 0; s < NS; s++) { sc[s] = __expf(sc[s] - mx); den += sc[s]; }
        float inv = 1.0f / den;
        float ra = 0.0f, rb = 0.0f;
#pragma unroll
        for (int s = 0; s < NS; s++) {
            float w = sc[s] * inv;
            ra = fmaf(w, bka[s], ra);
            rb = fmaf(w, bkb[s], rb);
        }
        float mu = wsum(ra + rb) * (1.0f / 64.0f);
        float da = ra - mu, db = rb - mu;
        float var = wsum(da * da + db * db) * (1.0f / 64.0f);
        float rstd = rsqrtf(var + 1e-5f);
        g_tree[obase + q * 64 + lane]      = da * rstd * gma + bta + sa * ska;
        g_tree[obase + q * 64 + lane + 32] = db * rstd * gmb + btb + sa * skb;
    }
}

// ---------------- cover attention: one warp per (t,b,h) ----------------
__global__ void cover_attn_kernel()
{
    int t = blockIdx.x, b = blockIdx.y;
    int h = threadIdx.x >> 5, lane = threadIdx.x & 31;
    int pos = t + 1;
    const float* qb = g_qall + (size_t)(b * LL + t) * (NDUSED * DMODEL) + h * 64;

    float m = -1e30f, den = 0.0f, ca = 0.0f, cb = 0.0f;
#pragma unroll
    for (int s = 0; s < 12; s++) {
        if ((pos >> s) & 1) {
            int node = ((LEAF + pos) >> s) - 1;
            const float* qp = qb + s * DMODEL;
            float qa = qp[lane], qv = qp[lane + 32];
            float scl = g_scale[s];
            const float* vp = g_tree + (size_t)((node * 2 + b) * 8 + h) * 128;
            int kv = (s == 0) ? 1 : 2;
            for (int k = 0; k < kv; k++) {
                float va = vp[k * 64 + lane], vb = vp[k * 64 + lane + 32];
                float dot = wsum(qa * va + qv * vb) * scl;
                float nm = fmaxf(m, dot);
                float f = __expf(m - nm);
                float e = __expf(dot - nm);
                den = den * f + e;
                ca = ca * f + e * va;
                cb = cb * f + e * vb;
                m = nm;
            }
        }
    }
    float inv = 1.0f / den;
    size_t o = (size_t)(b * LL + t) * DMODEL + h * 64;
    g_ctx[o + lane] = ca * inv;
    g_ctx[o + lane + 32] = cb * inv;
}

// ---------------- launcher ----------------
extern "C" void kernel_launch(void* const* d_in, const int* in_sizes, int n_in,
                              void* d_out, int out_size)
{
    const float* x      = (const float*)d_in[0];
    const float* Wq     = (const float*)d_in[1];
    const float* Wv     = (const float*)d_in[2];
    const float* Wo     = (const float*)d_in[3];
    const float* glw    = (const float*)d_in[4];
    const float* glb    = (const float*)d_in[5];
    const float* grw    = (const float*)d_in[6];
    const float* grb    = (const float*)d_in[7];
    const float* pqb    = (const float*)d_in[8];
    const float* qow    = (const float*)d_in[9];
    const float* qob    = (const float*)d_in[10];
    const float* lng    = (const float*)d_in[11];
    const float* lnb    = (const float*)d_in[12];
    const float* skw    = (const float*)d_in[13];
    const float* salpha = (const float*)d_in[14];
    const float* wfreq  = (const float*)d_in[15];
    const float* wdamp  = (const float*)d_in[16];
    const float* wphase = (const float*)d_in[17];
    const float* dpw    = (const float*)d_in[18];
    const float* dtemp  = (const float*)d_in[19];

    precompute_kernel<<<1, 256>>>(glw, grw, pqb, qow, qob, skw, salpha,
                                  wfreq, wdamp, wphase, dtemp);

    // q_base = x @ Wq^T ; v -> tree leaves = x @ Wv^T
    gemm_kernel<2, 0><<<dim3(32, 8), 256>>>(x, Wq, nullptr, BB * LL, DMODEL, DMODEL);
    gemm_kernel<1, 0><<<dim3(32, 8), 256>>>(x, Wv, nullptr, BB * LL, DMODEL, DMODEL);

    // q_all for depths 0..11
    qproj_kernel<<<512, 256>>>(dpw);

    // tree merges, levels 1..11 (root unused by covers)
    for (int d = 1; d <= 11; d++) {
        int lo = 1 << (12 - d);
        int total = lo * 16;
        int blocks = (total + 7) / 8;
        if (d == 1) merge_kernel<1><<<blocks, 256>>>(d, lo, glb, grb, lng, lnb);
        else        merge_kernel<2><<<blocks, 256>>>(d, lo, glb, grb, lng, lnb);
    }

    // cover attention -> ctx
    cover_attn_kernel<<<dim3(LL, BB), 256>>>();

    // out = ctx @ Wo^T
    gemm_kernel<0, 1><<<dim3(32, 8), 256>>>(nullptr, Wo, (float*)d_out, BB * LL, DMODEL, DMODEL);
}

// round 5
// speedup vs baseline: 1.0746x; 1.0746x over previous
#include <cuda_runtime.h>
#include <stdint.h>
#include <math.h>

// ---------------- problem constants ----------------
#define BB 2
#define LL 2048
#define HH 8
#define DD 64
#define KMAX 2
#define EE 32
#define LOGN 12
#define LEAF 4096
#define NDUSED 12
#define DMODEL 512

// ---------------- device scratch (static, no allocs) ----------------
__device__ float g_tree[8192 * BB * HH * KMAX * DD];          // 64 MB
__device__ float g_qbase[BB * LL * DMODEL];                   // 8 MB
__device__ float g_qall[BB * LL * NDUSED * DMODEL];           // 100 MB  (b,l,s,h,d)
__device__ float g_ctx[BB * LL * DMODEL];                     // 8 MB

__device__ float4 g_gw[160][32];
__device__ float2 g_skw[64][32];
__device__ float  g_dv[13][32];
__device__ float  g_pr[13][8];
__device__ float  g_pi[13][8];
__device__ float  g_pq[13][2][64];
__device__ float  g_scale[13];
__device__ float  g_sigalpha;

// ---------------- helpers ----------------
__device__ __forceinline__ float wsum(float v) {
    v += __shfl_xor_sync(0xffffffffu, v, 16);
    v += __shfl_xor_sync(0xffffffffu, v, 8);
    v += __shfl_xor_sync(0xffffffffu, v, 4);
    v += __shfl_xor_sync(0xffffffffu, v, 2);
    v += __shfl_xor_sync(0xffffffffu, v, 1);
    return v;
}
__device__ __forceinline__ float sigf(float x) { return 1.0f / (1.0f + __expf(-x)); }

// ---------------- precompute small tables ----------------
__global__ void precompute_kernel(
    const float* __restrict__ glw, const float* __restrict__ grw,
    const float* __restrict__ pqb, const float* __restrict__ qow,
    const float* __restrict__ qob, const float* __restrict__ skw,
    const float* __restrict__ salpha, const float* __restrict__ wfreq,
    const float* __restrict__ wdamp, const float* __restrict__ wphase,
    const float* __restrict__ dtemp)
{
    int t = threadIdx.x;  // 256 threads

    for (int idx = t; idx < 160 * 32; idx += 256) {
        int i = idx >> 5, l = idx & 31;
        g_gw[i][l] = make_float4(glw[l * 160 + i], glw[(l + 32) * 160 + i],
                                 grw[l * 160 + i], grw[(l + 32) * 160 + i]);
    }
    for (int idx = t; idx < 64 * 32; idx += 256) {
        int i = idx >> 5, l = idx & 31;
        g_skw[i][l] = make_float2(skw[l * 64 + i], skw[(l + 32) * 64 + i]);
    }
    for (int idx = t; idx < 13 * 32; idx += 256) {
        int d = idx >> 5, e = idx & 31;
        int i = e >> 1;
        float inv = expf(-(2.0f * (float)i) * logf(10000.0f) / 32.0f);
        float a = (float)d * inv;
        g_dv[d][e] = (e & 1) ? cosf(a) : sinf(a);
    }
    if (t < 13 * 8) {
        int d = t >> 3, h = t & 7;
        float sp = log1pf(expf(wdamp[h]));
        float decay = expf(-sp);
        float ang = wfreq[h] + wphase[h] + (float)d * 0.78539816339744831f;
        g_pr[d][h] = decay * cosf(ang);
        g_pi[d][h] = decay * sinf(ang);
    }
    if (t < 13) {
        float sp = log1pf(expf(dtemp[t]));
        g_scale[t] = 1.0f / ((sp + 1e-6f) * 8.0f);
    }
    if (t == 0) g_sigalpha = 1.0f / (1.0f + expf(-salpha[0]));

    __syncthreads();

    for (int idx = t; idx < 13 * 128; idx += 256) {
        int d = idx >> 7, kj = idx & 127;
        float s = pqb[kj] + qob[kj];
        for (int e = 0; e < 32; e++) s += qow[kj * 32 + e] * g_dv[d][e];
        g_pq[d][kj >> 6][kj & 63] = s;
    }
}

// ---------------- fp32 SIMT GEMM (round-1 verified): C = A(MxK) @ W(NxK)^T ----------------
template <int MODE, int ASRC>
__global__ void gemm_kernel(const float* __restrict__ A, const float* __restrict__ W,
                            float* __restrict__ C, int M, int N, int K)
{
    __shared__ float As[16][132];
    __shared__ float Ws[16][68];
    const float* Ab = (ASRC == 0) ? A : g_ctx;
    int t = threadIdx.x;
    int tx = t & 15, ty = t >> 4;
    int m0 = blockIdx.x * 128, n0 = blockIdx.y * 64;

    float acc[8][4];
#pragma unroll
    for (int i = 0; i < 8; i++)
#pragma unroll
        for (int j = 0; j < 4; j++) acc[i][j] = 0.0f;

    for (int k0 = 0; k0 < K; k0 += 16) {
#pragma unroll
        for (int j = 0; j < 2; j++) {
            int q = t + 256 * j;
            int r = q >> 2, kq = q & 3;
            float4 v = *(const float4*)(Ab + (size_t)(m0 + r) * K + k0 + kq * 4);
            As[kq * 4 + 0][r] = v.x; As[kq * 4 + 1][r] = v.y;
            As[kq * 4 + 2][r] = v.z; As[kq * 4 + 3][r] = v.w;
        }
        {
            int n = t >> 2, kq = t & 3;
            float4 v = *(const float4*)(W + (size_t)(n0 + n) * K + k0 + kq * 4);
            Ws[kq * 4 + 0][n] = v.x; Ws[kq * 4 + 1][n] = v.y;
            Ws[kq * 4 + 2][n] = v.z; Ws[kq * 4 + 3][n] = v.w;
        }
        __syncthreads();
#pragma unroll
        for (int kk = 0; kk < 16; kk++) {
            float4 a0 = *(const float4*)&As[kk][ty * 8];
            float4 a1 = *(const float4*)&As[kk][ty * 8 + 4];
            float4 bv = *(const float4*)&Ws[kk][tx * 4];
            float av[8] = {a0.x, a0.y, a0.z, a0.w, a1.x, a1.y, a1.z, a1.w};
            float bw[4] = {bv.x, bv.y, bv.z, bv.w};
#pragma unroll
            for (int i = 0; i < 8; i++)
#pragma unroll
                for (int j = 0; j < 4; j++) acc[i][j] = fmaf(av[i], bw[j], acc[i][j]);
        }
        __syncthreads();
    }

    if (MODE == 0) {
#pragma unroll
        for (int i = 0; i < 8; i++) {
            float4 v = make_float4(acc[i][0], acc[i][1], acc[i][2], acc[i][3]);
            *(float4*)(C + (size_t)(m0 + ty * 8 + i) * N + n0 + tx * 4) = v;
        }
    } else if (MODE == 2) {
#pragma unroll
        for (int i = 0; i < 8; i++) {
            float4 v = make_float4(acc[i][0], acc[i][1], acc[i][2], acc[i][3]);
            *(float4*)(g_qbase + (size_t)(m0 + ty * 8 + i) * DMODEL + n0 + tx * 4) = v;
        }
    } else {
        int n = n0 + tx * 4;
        int hh = n >> 6, dd = n & 63;
#pragma unroll
        for (int i = 0; i < 8; i++) {
            int mm = m0 + ty * 8 + i;
            int bb = mm >> 11, ll = mm & 2047;
            float* p = g_tree + (size_t)((((LEAF + ll) * 2 + bb) * 8 + hh)) * 128 + dd;
            *(float4*)p = make_float4(acc[i][0], acc[i][1], acc[i][2], acc[i][3]);
        }
    }
}

// ---------------- q_all: per depth n, q_all[n] = q_base + q_base @ W[n]^T (round-1 verified) ----------------
__global__ void qproj_kernel(const float* __restrict__ dpw)
{
    __shared__ float As[64][68];
    __shared__ float Ws[64][68];
    int t = threadIdx.x;
    int tx = t & 15, ty = t >> 4;
    int row0 = blockIdx.x * 64;

#pragma unroll
    for (int j = 0; j < 4; j++) {
        int q = t + 256 * j;
        int r = q >> 4, dq = q & 15;
        float4 v = *(const float4*)(g_qbase + (size_t)(row0 + r) * 64 + dq * 4);
        As[dq * 4 + 0][r] = v.x; As[dq * 4 + 1][r] = v.y;
        As[dq * 4 + 2][r] = v.z; As[dq * 4 + 3][r] = v.w;
    }

    for (int n = 0; n < NDUSED; n++) {
        __syncthreads();
        const float* W = dpw + (size_t)n * 4096;
#pragma unroll
        for (int j = 0; j < 4; j++) {
            int q = t + 256 * j;
            int o = q >> 4, dq = q & 15;
            float4 v = *(const float4*)(W + (size_t)o * 64 + dq * 4);
            Ws[dq * 4 + 0][o] = v.x; Ws[dq * 4 + 1][o] = v.y;
            Ws[dq * 4 + 2][o] = v.z; Ws[dq * 4 + 3][o] = v.w;
        }
        __syncthreads();

        float acc[4][4];
#pragma unroll
        for (int i = 0; i < 4; i++)
#pragma unroll
            for (int j = 0; j < 4; j++) acc[i][j] = 0.0f;

#pragma unroll 8
        for (int dd = 0; dd < 64; dd++) {
            float4 a = *(const float4*)&As[dd][ty * 4];
            float4 b = *(const float4*)&Ws[dd][tx * 4];
            float av[4] = {a.x, a.y, a.z, a.w};
            float bw[4] = {b.x, b.y, b.z, b.w};
#pragma unroll
            for (int i = 0; i < 4; i++)
#pragma unroll
                for (int j = 0; j < 4; j++) acc[i][j] = fmaf(av[i], bw[j], acc[i][j]);
        }
#pragma unroll
        for (int i = 0; i < 4; i++)
#pragma unroll
            for (int j = 0; j < 4; j++) acc[i][j] += As[tx * 4 + j][ty * 4 + i];
#pragma unroll
        for (int i = 0; i < 4; i++) {
            int rg = row0 + ty * 4 + i;
            int bl = rg >> 3, hh = rg & 7;
            float4 v = make_float4(acc[i][0], acc[i][1], acc[i][2], acc[i][3]);
            *(float4*)(g_qall + ((size_t)(bl * NDUSED + n) * 8 + hh) * 64 + tx * 4) = v;
        }
    }
}

// ---------------- tree merge: one warp per (node,h), both b fused (THE single change) ----------------
template <int KC>
__global__ void merge_kernel(int d, int lo,
                             const float* __restrict__ glb, const float* __restrict__ grb,
                             const float* __restrict__ ln_g, const float* __restrict__ ln_b)
{
    constexpr int NS = 2 * KC;
    __shared__ float s_gin[8][2][160];
    int warp = threadIdx.x >> 5;
    int lane = threadIdx.x & 31;
    int inst = blockIdx.x * 8 + warp;      // (node-lo)*8 + h
    if (inst >= lo * 8) return;
    int node = lo + (inst >> 3);
    int h = inst & 7;

    float pr = g_pr[d][h], pi = g_pi[d][h];
    float fla[2][KC], flb[2][KC], rta[2][KC], rtb[2][KC];
#pragma unroll
    for (int b = 0; b < 2; b++) {
        const float* tl = g_tree + (size_t)(((2 * node) * 2 + b) * 8 + h) * 128;
        const float* tr = g_tree + (size_t)(((2 * node + 1) * 2 + b) * 8 + h) * 128;
#pragma unroll
        for (int k = 0; k < KC; k++) {
            fla[b][k] = tl[k * 64 + lane];
            flb[b][k] = tl[k * 64 + lane + 32];
            float fr = tr[k * 64 + lane];
            float fi = tr[k * 64 + lane + 32];
            rta[b][k] = pr * fr - pi * fi;
            rtb[b][k] = pi * fr + pr * fi;
        }
        float lma, lmb, rma, rmb;
        if (KC == 2) {
            lma = 0.5f * (fla[b][0] + fla[b][1]); lmb = 0.5f * (flb[b][0] + flb[b][1]);
            rma = 0.5f * (rta[b][0] + rta[b][1]); rmb = 0.5f * (rtb[b][0] + rtb[b][1]);
        } else {
            lma = fla[b][0]; lmb = flb[b][0]; rma = rta[b][0]; rmb = rtb[b][0];
        }
        float* gin = s_gin[warp][b];
        gin[lane] = lma; gin[lane + 32] = lmb;
        gin[64 + lane] = rma; gin[96 + lane] = rmb;
        gin[128 + lane] = g_dv[d][lane];
    }
    __syncwarp();

    float al0[2], al1[2], ar0[2], ar1[2];
#pragma unroll
    for (int b = 0; b < 2; b++) {
        al0[b] = glb[lane]; al1[b] = glb[lane + 32];
        ar0[b] = grb[lane]; ar1[b] = grb[lane + 32];
    }
#pragma unroll 4
    for (int i = 0; i < 160; i++) {
        float4 w = g_gw[i][lane];
#pragma unroll
        for (int b = 0; b < 2; b++) {
            float gi = s_gin[warp][b][i];
            al0[b] = fmaf(w.x, gi, al0[b]); al1[b] = fmaf(w.y, gi, al1[b]);
            ar0[b] = fmaf(w.z, gi, ar0[b]); ar1[b] = fmaf(w.w, gi, ar1[b]);
        }
    }

    float ska[2], skb[2];
    ska[0] = ska[1] = skb[0] = skb[1] = 0.0f;
#pragma unroll 4
    for (int i = 0; i < 64; i++) {
        float2 w = g_skw[i][lane];
#pragma unroll
        for (int b = 0; b < 2; b++) {
            float l = s_gin[warp][b][i];
            ska[b] = fmaf(w.x, l, ska[b]);
            skb[b] = fmaf(w.y, l, skb[b]);
        }
    }

    float sa = g_sigalpha;
    float gma = ln_g[lane], gmb = ln_g[lane + 32];
    float bta = ln_b[lane], btb = ln_b[lane + 32];

#pragma unroll
    for (int b = 0; b < 2; b++) {
        float gla = sigf(al0[b]), glv = sigf(al1[b]);
        float gra = sigf(ar0[b]), grv = sigf(ar1[b]);

        float bka[NS], bkb[NS];
#pragma unroll
        for (int k = 0; k < KC; k++) {
            bka[k] = fla[b][k] * gla;      bkb[k] = flb[b][k] * glv;
            bka[KC + k] = rta[b][k] * gra; bkb[KC + k] = rtb[b][k] * grv;
        }
        size_t obase = (size_t)((node * 2 + b) * 8 + h) * 128;

#pragma unroll
        for (int q = 0; q < 2; q++) {
            float pqa = g_pq[d][q][lane], pqb = g_pq[d][q][lane + 32];
            float sc[NS];
#pragma unroll
            for (int s = 0; s < NS; s++) {
                float p = pqa * bka[s] + pqb * bkb[s];
                sc[s] = wsum(p) * 0.125f;
            }
            float mx = sc[0];
#pragma unroll
            for (int s = 1; s < NS; s++) mx = fmaxf(mx, sc[s]);
            float den = 0.0f;
#pragma unroll
            for (int s = 0; s < NS; s++) { sc[s] = __expf(sc[s] - mx); den += sc[s]; }
            float inv = 1.0f / den;
            float ra = 0.0f, rb = 0.0f;
#pragma unroll
            for (int s = 0; s < NS; s++) {
                float w = sc[s] * inv;
                ra = fmaf(w, bka[s], ra);
                rb = fmaf(w, bkb[s], rb);
            }
            float mu = wsum(ra + rb) * (1.0f / 64.0f);
            float da = ra - mu, db = rb - mu;
            float var = wsum(da * da + db * db) * (1.0f / 64.0f);
            float rstd = rsqrtf(var + 1e-5f);
            g_tree[obase + q * 64 + lane]      = da * rstd * gma + bta + sa * ska[b];
            g_tree[obase + q * 64 + lane + 32] = db * rstd * gmb + btb + sa * skb[b];
        }
    }
}

// ---------------- cover attention (round-1 verified): one warp per (t,b,h) ----------------
__global__ void cover_attn_kernel()
{
    int t = blockIdx.x, b = blockIdx.y;
    int h = threadIdx.x >> 5, lane = threadIdx.x & 31;
    int pos = t + 1;
    const float* qb = g_qall + (size_t)(b * LL + t) * (NDUSED * DMODEL) + h * 64;

    float m = -1e30f, den = 0.0f, ca = 0.0f, cb = 0.0f;
#pragma unroll
    for (int s = 0; s < 12; s++) {
        if ((pos >> s) & 1) {
            int node = ((LEAF + pos) >> s) - 1;
            const float* qp = qb + s * DMODEL;
            float qa = qp[lane], qv = qp[lane + 32];
            float scl = g_scale[s];
            const float* vp = g_tree + (size_t)((node * 2 + b) * 8 + h) * 128;
            int kv = (s == 0) ? 1 : 2;
            for (int k = 0; k < kv; k++) {
                float va = vp[k * 64 + lane], vb = vp[k * 64 + lane + 32];
                float dot = wsum(qa * va + qv * vb) * scl;
                float nm = fmaxf(m, dot);
                float f = __expf(m - nm);
                float e = __expf(dot - nm);
                den = den * f + e;
                ca = ca * f + e * va;
                cb = cb * f + e * vb;
                m = nm;
            }
        }
    }
    float inv = 1.0f / den;
    size_t o = (size_t)(b * LL + t) * DMODEL + h * 64;
    g_ctx[o + lane] = ca * inv;
    g_ctx[o + lane + 32] = cb * inv;
}

// ---------------- launcher ----------------
extern "C" void kernel_launch(void* const* d_in, const int* in_sizes, int n_in,
                              void* d_out, int out_size)
{
    const float* x      = (const float*)d_in[0];
    const float* Wq     = (const float*)d_in[1];
    const float* Wv     = (const float*)d_in[2];
    const float* Wo     = (const float*)d_in[3];
    const float* glw    = (const float*)d_in[4];
    const float* glb    = (const float*)d_in[5];
    const float* grw    = (const float*)d_in[6];
    const float* grb    = (const float*)d_in[7];
    const float* pqb    = (const float*)d_in[8];
    const float* qow    = (const float*)d_in[9];
    const float* qob    = (const float*)d_in[10];
    const float* lng    = (const float*)d_in[11];
    const float* lnb    = (const float*)d_in[12];
    const float* skw    = (const float*)d_in[13];
    const float* salpha = (const float*)d_in[14];
    const float* wfreq  = (const float*)d_in[15];
    const float* wdamp  = (const float*)d_in[16];
    const float* wphase = (const float*)d_in[17];
    const float* dpw    = (const float*)d_in[18];
    const float* dtemp  = (const float*)d_in[19];

    precompute_kernel<<<1, 256>>>(glw, grw, pqb, qow, qob, skw, salpha,
                                  wfreq, wdamp, wphase, dtemp);

    gemm_kernel<2, 0><<<dim3(32, 8), 256>>>(x, Wq, nullptr, BB * LL, DMODEL, DMODEL);
    gemm_kernel<1, 0><<<dim3(32, 8), 256>>>(x, Wv, nullptr, BB * LL, DMODEL, DMODEL);

    qproj_kernel<<<512, 256>>>(dpw);

    for (int d = 1; d <= 11; d++) {
        int lo = 1 << (12 - d);
        if (d == 1) merge_kernel<1><<<lo, 256>>>(d, lo, glb, grb, lng, lnb);
        else        merge_kernel<2><<<lo, 256>>>(d, lo, glb, grb, lng, lnb);
    }

    cover_attn_kernel<<<dim3(LL, BB), 256>>>();

    gemm_kernel<0, 1><<<dim3(32, 8), 256>>>(nullptr, Wo, (float*)d_out, BB * LL, DMODEL, DMODEL);
}

// round 7
// speedup vs baseline: 1.4342x; 1.3347x over previous
#include <cuda_runtime.h>
#include <cuda_bf16.h>
#include <stdint.h>
#include <math.h>

// ---------------- problem constants ----------------
#define BB 2
#define LL 2048
#define HH 8
#define DMODEL 512
#define LEAF 4096

// ---------------- device scratch (static, no allocs) ----------------
__device__ float g_tree[8192 * 2 * 8 * 2 * 64];   // 64 MB  (node,b,h,k,d)
__device__ float g_u   [8192 * 2 * 8 * 2 * 64];   // 64 MB  u = W_s^T v on cover nodes
__device__ float g_qbase[BB * LL * DMODEL];       // 8 MB
__device__ float g_ctx[BB * LL * DMODEL];         // 8 MB

__device__ float4 g_gw[160][32];
__device__ float2 g_skw[64][32];
__device__ float  g_dv[13][32];
__device__ float  g_pr[13][8];
__device__ float  g_pi[13][8];
__device__ float  g_pq[13][2][64];
__device__ float  g_scale[13];
__device__ float  g_sigalpha;

// ---------------- helpers ----------------
__device__ __forceinline__ float wsum(float v) {
    v += __shfl_xor_sync(0xffffffffu, v, 16);
    v += __shfl_xor_sync(0xffffffffu, v, 8);
    v += __shfl_xor_sync(0xffffffffu, v, 4);
    v += __shfl_xor_sync(0xffffffffu, v, 2);
    v += __shfl_xor_sync(0xffffffffu, v, 1);
    return v;
}
__device__ __forceinline__ float sigf(float x) { return 1.0f / (1.0f + __expf(-x)); }

__device__ __forceinline__ void split2(float x, float y, unsigned int& hp, unsigned int& lp) {
    __nv_bfloat162 hh, ll;
    hh.x = __float2bfloat16(x);
    hh.y = __float2bfloat16(y);
    ll.x = __float2bfloat16(x - __bfloat162float(hh.x));
    ll.y = __float2bfloat16(y - __bfloat162float(hh.y));
    hp = *reinterpret_cast<unsigned int*>(&hh);
    lp = *reinterpret_cast<unsigned int*>(&ll);
}

__device__ __forceinline__ void mma_bf16(float* c, const unsigned int* a, const unsigned int* b) {
    asm volatile(
        "mma.sync.aligned.m16n8k16.row.col.f32.bf16.bf16.f32 "
        "{%0,%1,%2,%3}, {%4,%5,%6,%7}, {%8,%9}, {%0,%1,%2,%3};"
        : "+f"(c[0]), "+f"(c[1]), "+f"(c[2]), "+f"(c[3])
        : "r"(a[0]), "r"(a[1]), "r"(a[2]), "r"(a[3]), "r"(b[0]), "r"(b[1]));
}

// ---------------- precompute small tables ----------------
__global__ void precompute_kernel(
    const float* __restrict__ glw, const float* __restrict__ grw,
    const float* __restrict__ pqb, const float* __restrict__ qow,
    const float* __restrict__ qob, const float* __restrict__ skw,
    const float* __restrict__ salpha, const float* __restrict__ wfreq,
    const float* __restrict__ wdamp, const float* __restrict__ wphase,
    const float* __restrict__ dtemp)
{
    int t = threadIdx.x;  // 256 threads

    for (int idx = t; idx < 160 * 32; idx += 256) {
        int i = idx >> 5, l = idx & 31;
        g_gw[i][l] = make_float4(glw[l * 160 + i], glw[(l + 32) * 160 + i],
                                 grw[l * 160 + i], grw[(l + 32) * 160 + i]);
    }
    for (int idx = t; idx < 64 * 32; idx += 256) {
        int i = idx >> 5, l = idx & 31;
        g_skw[i][l] = make_float2(skw[l * 64 + i], skw[(l + 32) * 64 + i]);
    }
    for (int idx = t; idx < 13 * 32; idx += 256) {
        int d = idx >> 5, e = idx & 31;
        int i = e >> 1;
        float inv = expf(-(2.0f * (float)i) * logf(10000.0f) / 32.0f);
        float a = (float)d * inv;
        g_dv[d][e] = (e & 1) ? cosf(a) : sinf(a);
    }
    if (t < 13 * 8) {
        int d = t >> 3, h = t & 7;
        float sp = log1pf(expf(wdamp[h]));
        float decay = expf(-sp);
        float ang = wfreq[h] + wphase[h] + (float)d * 0.78539816339744831f;
        g_pr[d][h] = decay * cosf(ang);
        g_pi[d][h] = decay * sinf(ang);
    }
    if (t < 13) {
        float sp = log1pf(expf(dtemp[t]));
        g_scale[t] = 1.0f / ((sp + 1e-6f) * 8.0f);
    }
    if (t == 0) g_sigalpha = 1.0f / (1.0f + expf(-salpha[0]));

    __syncthreads();

    for (int idx = t; idx < 13 * 128; idx += 256) {
        int d = idx >> 7, kj = idx & 127;
        float s = pqb[kj] + qob[kj];
        for (int e = 0; e < 32; e++) s += qow[kj * 32 + e] * g_dv[d][e];
        g_pq[d][kj >> 6][kj & 63] = s;
    }
}

// ---------------- bf16-split tensor-core GEMM: C = A(4096x512) @ W(512x512)^T ----------------
// Validated vs fp32 in rounds 3/4 (outputs matched to 7th digit).
// MODE: 0 -> C param; 1 -> scatter into tree leaves; 2 -> write g_qbase
// ASRC: 0 -> A param; 1 -> A = g_ctx
template <int MODE, int ASRC>
__global__ void __launch_bounds__(256) gemm_bf16s(const float* __restrict__ A,
                                                  const float* __restrict__ W,
                                                  float* __restrict__ C)
{
    __shared__ unsigned int Ah[128][12], Al[128][12], Bh[128][12], Bl[128][12];
    const float* Ab = (ASRC == 0) ? A : g_ctx;
    int t = threadIdx.x;
    int lane = t & 31, wid = t >> 5;
    int wm = (wid & 1) * 64, wn = (wid >> 1) * 32;
    int m0 = blockIdx.x * 128, n0 = blockIdx.y * 128;
    int g = lane >> 2, tq = lane & 3;

    float c[4][4][4];
#pragma unroll
    for (int i = 0; i < 4; i++)
#pragma unroll
        for (int j = 0; j < 4; j++)
#pragma unroll
            for (int k = 0; k < 4; k++) c[i][j][k] = 0.0f;

    for (int k0 = 0; k0 < DMODEL; k0 += 16) {
#pragma unroll
        for (int j = 0; j < 2; j++) {
            int q = t + 256 * j;
            int row = q >> 2, kq = q & 3;
            float4 va = *(const float4*)(Ab + (size_t)(m0 + row) * DMODEL + k0 + kq * 4);
            unsigned int hp, lp;
            split2(va.x, va.y, hp, lp); Ah[row][kq * 2] = hp;     Al[row][kq * 2] = lp;
            split2(va.z, va.w, hp, lp); Ah[row][kq * 2 + 1] = hp; Al[row][kq * 2 + 1] = lp;
            float4 vb = *(const float4*)(W + (size_t)(n0 + row) * DMODEL + k0 + kq * 4);
            split2(vb.x, vb.y, hp, lp); Bh[row][kq * 2] = hp;     Bl[row][kq * 2] = lp;
            split2(vb.z, vb.w, hp, lp); Bh[row][kq * 2 + 1] = hp; Bl[row][kq * 2 + 1] = lp;
        }
        __syncthreads();

        unsigned int ah[4][4], al[4][4], bh[4][2], bl[4][2];
#pragma unroll
        for (int mt = 0; mt < 4; mt++) {
            int r = wm + mt * 16 + g;
            ah[mt][0] = Ah[r][tq];     ah[mt][1] = Ah[r + 8][tq];
            ah[mt][2] = Ah[r][tq + 4]; ah[mt][3] = Ah[r + 8][tq + 4];
            al[mt][0] = Al[r][tq];     al[mt][1] = Al[r + 8][tq];
            al[mt][2] = Al[r][tq + 4]; al[mt][3] = Al[r + 8][tq + 4];
        }
#pragma unroll
        for (int nt = 0; nt < 4; nt++) {
            int n = wn + nt * 8 + g;
            bh[nt][0] = Bh[n][tq]; bh[nt][1] = Bh[n][tq + 4];
            bl[nt][0] = Bl[n][tq]; bl[nt][1] = Bl[n][tq + 4];
        }
#pragma unroll
        for (int mt = 0; mt < 4; mt++)
#pragma unroll
            for (int nt = 0; nt < 4; nt++) {
                mma_bf16(c[mt][nt], ah[mt], bh[nt]);
                mma_bf16(c[mt][nt], al[mt], bh[nt]);
                mma_bf16(c[mt][nt], ah[mt], bl[nt]);
            }
        __syncthreads();
    }

#pragma unroll
    for (int mt = 0; mt < 4; mt++)
#pragma unroll
        for (int nt = 0; nt < 4; nt++) {
            int r0 = m0 + wm + mt * 16 + g;
            int cc = n0 + wn + nt * 8 + tq * 2;
            float2 v0 = make_float2(c[mt][nt][0], c[mt][nt][1]);
            float2 v1 = make_float2(c[mt][nt][2], c[mt][nt][3]);
            if (MODE == 0) {
                *(float2*)(C + (size_t)r0 * DMODEL + cc) = v0;
                *(float2*)(C + (size_t)(r0 + 8) * DMODEL + cc) = v1;
            } else if (MODE == 2) {
                *(float2*)(g_qbase + (size_t)r0 * DMODEL + cc) = v0;
                *(float2*)(g_qbase + (size_t)(r0 + 8) * DMODEL + cc) = v1;
            } else {
                int hh = cc >> 6, dd = cc & 63;
                int b0 = r0 >> 11, l0 = r0 & 2047;
                *(float2*)(g_tree + ((size_t)(((LEAF + l0) * 2 + b0) * 8 + hh)) * 128 + dd) = v0;
                int r1 = r0 + 8;
                int b1 = r1 >> 11, l1 = r1 & 2047;
                *(float2*)(g_tree + ((size_t)(((LEAF + l1) * 2 + b1) * 8 + hh)) * 128 + dd) = v1;
            }
        }
}

// ---------------- tree merge: one warp per (node,h), both b fused (round-5 verified) ----------------
template <int KC>
__global__ void merge_kernel(int d, int lo,
                             const float* __restrict__ glb, const float* __restrict__ grb,
                             const float* __restrict__ ln_g, const float* __restrict__ ln_b)
{
    constexpr int NS = 2 * KC;
    __shared__ float s_gin[8][2][160];
    int warp = threadIdx.x >> 5;
    int lane = threadIdx.x & 31;
    int inst = blockIdx.x * 8 + warp;
    if (inst >= lo * 8) return;
    int node = lo + (inst >> 3);
    int h = inst & 7;

    float pr = g_pr[d][h], pi = g_pi[d][h];
    float fla[2][KC], flb[2][KC], rta[2][KC], rtb[2][KC];
#pragma unroll
    for (int b = 0; b < 2; b++) {
        const float* tl = g_tree + (size_t)(((2 * node) * 2 + b) * 8 + h) * 128;
        const float* tr = g_tree + (size_t)(((2 * node + 1) * 2 + b) * 8 + h) * 128;
#pragma unroll
        for (int k = 0; k < KC; k++) {
            fla[b][k] = tl[k * 64 + lane];
            flb[b][k] = tl[k * 64 + lane + 32];
            float fr = tr[k * 64 + lane];
            float fi = tr[k * 64 + lane + 32];
            rta[b][k] = pr * fr - pi * fi;
            rtb[b][k] = pi * fr + pr * fi;
        }
        float lma, lmb, rma, rmb;
        if (KC == 2) {
            lma = 0.5f * (fla[b][0] + fla[b][1]); lmb = 0.5f * (flb[b][0] + flb[b][1]);
            rma = 0.5f * (rta[b][0] + rta[b][1]); rmb = 0.5f * (rtb[b][0] + rtb[b][1]);
        } else {
            lma = fla[b][0]; lmb = flb[b][0]; rma = rta[b][0]; rmb = rtb[b][0];
        }
        float* gin = s_gin[warp][b];
        gin[lane] = lma; gin[lane + 32] = lmb;
        gin[64 + lane] = rma; gin[96 + lane] = rmb;
        gin[128 + lane] = g_dv[d][lane];
    }
    __syncwarp();

    float al0[2], al1[2], ar0[2], ar1[2];
#pragma unroll
    for (int b = 0; b < 2; b++) {
        al0[b] = glb[lane]; al1[b] = glb[lane + 32];
        ar0[b] = grb[lane]; ar1[b] = grb[lane + 32];
    }
#pragma unroll 4
    for (int i = 0; i < 160; i++) {
        float4 w = g_gw[i][lane];
#pragma unroll
        for (int b = 0; b < 2; b++) {
            float gi = s_gin[warp][b][i];
            al0[b] = fmaf(w.x, gi, al0[b]); al1[b] = fmaf(w.y, gi, al1[b]);
            ar0[b] = fmaf(w.z, gi, ar0[b]); ar1[b] = fmaf(w.w, gi, ar1[b]);
        }
    }

    float ska[2], skb[2];
    ska[0] = ska[1] = skb[0] = skb[1] = 0.0f;
#pragma unroll 4
    for (int i = 0; i < 64; i++) {
        float2 w = g_skw[i][lane];
#pragma unroll
        for (int b = 0; b < 2; b++) {
            float l = s_gin[warp][b][i];
            ska[b] = fmaf(w.x, l, ska[b]);
            skb[b] = fmaf(w.y, l, skb[b]);
        }
    }

    float sa = g_sigalpha;
    float gma = ln_g[lane], gmb = ln_g[lane + 32];
    float bta = ln_b[lane], btb = ln_b[lane + 32];

#pragma unroll
    for (int b = 0; b < 2; b++) {
        float gla = sigf(al0[b]), glv = sigf(al1[b]);
        float gra = sigf(ar0[b]), grv = sigf(ar1[b]);

        float bka[NS], bkb[NS];
#pragma unroll
        for (int k = 0; k < KC; k++) {
            bka[k] = fla[b][k] * gla;      bkb[k] = flb[b][k] * glv;
            bka[KC + k] = rta[b][k] * gra; bkb[KC + k] = rtb[b][k] * grv;
        }
        size_t obase = (size_t)((node * 2 + b) * 8 + h) * 128;

#pragma unroll
        for (int q = 0; q < 2; q++) {
            float pqa = g_pq[d][q][lane], pqb = g_pq[d][q][lane + 32];
            float sc[NS];
#pragma unroll
            for (int s = 0; s < NS; s++) {
                float p = pqa * bka[s] + pqb * bkb[s];
                sc[s] = wsum(p) * 0.125f;
            }
            float mx = sc[0];
#pragma unroll
            for (int s = 1; s < NS; s++) mx = fmaxf(mx, sc[s]);
            float den = 0.0f;
#pragma unroll
            for (int s = 0; s < NS; s++) { sc[s] = __expf(sc[s] - mx); den += sc[s]; }
            float inv = 1.0f / den;
            float ra = 0.0f, rb = 0.0f;
#pragma unroll
            for (int s = 0; s < NS; s++) {
                float w = sc[s] * inv;
                ra = fmaf(w, bka[s], ra);
                rb = fmaf(w, bkb[s], rb);
            }
            float mu = wsum(ra + rb) * (1.0f / 64.0f);
            float da = ra - mu, db = rb - mu;
            float var = wsum(da * da + db * db) * (1.0f / 64.0f);
            float rstd = rsqrtf(var + 1e-5f);
            g_tree[obase + q * 64 + lane]      = da * rstd * gma + bta + sa * ska[b];
            g_tree[obase + q * 64 + lane + 32] = db * rstd * gmb + btb + sa * skb[b];
        }
    }
}

// ---------------- u = W_s^T v for the 2048 cover-reachable (node,depth) entries ----------------
// u[d] = sum_o W[s][o][d] * v[o]   (FIXED: depth-binning loop now breaks once settled)
__global__ void utransform_kernel(const float* __restrict__ dpw)
{
    __shared__ float sv[8][4][64];
    int e = blockIdx.x;                    // 0..2047
    int h = threadIdx.x >> 5, lane = threadIdx.x & 31;

    int s = 0, base = 0;
#pragma unroll
    for (int ss = 0; ss < 12; ss++) {
        int cnt = 1024 >> ss; if (cnt == 0) cnt = 1;
        if (e >= base + cnt) { base += cnt; s = ss + 1; }
        else break;                        // <-- the fix
    }
    int node = (1 << (12 - s)) + 2 * (e - base);
    int kv = (s == 0) ? 1 : 2;
    int nvec = 2 * kv;
    const float* W = dpw + (size_t)s * 4096;

    for (int j = 0; j < nvec; j++) {
        int b = j / kv, k = j % kv;
        const float* src = g_tree + (size_t)((node * 2 + b) * 8 + h) * 128 + k * 64;
        sv[h][j][lane] = src[lane];
        sv[h][j][lane + 32] = src[lane + 32];
    }
    __syncwarp();

    float u0[4] = {0, 0, 0, 0}, u1[4] = {0, 0, 0, 0};
    for (int o = 0; o < 64; o++) {
        float w0 = W[o * 64 + lane];
        float w1 = W[o * 64 + lane + 32];
#pragma unroll
        for (int j = 0; j < 4; j++) {
            if (j < nvec) {
                float v = sv[h][j][o];
                u0[j] = fmaf(w0, v, u0[j]);
                u1[j] = fmaf(w1, v, u1[j]);
            }
        }
    }
    for (int j = 0; j < nvec; j++) {
        int b = j / kv, k = j % kv;
        float* dst = g_u + (size_t)((node * 2 + b) * 8 + h) * 128 + k * 64;
        dst[lane] = u0[j];
        dst[lane + 32] = u1[j];
    }
}

// ---------------- cover attention: one warp per (t,b,h), scores use q.(v+u) ----------------
__global__ void cover_attn_kernel()
{
    int t = blockIdx.x, b = blockIdx.y;
    int h = threadIdx.x >> 5, lane = threadIdx.x & 31;
    int pos = t + 1;
    const float* qp = g_qbase + (size_t)(b * LL + t) * DMODEL + h * 64;
    float qa = qp[lane], qb = qp[lane + 32];

    float m = -1e30f, den = 0.0f, ca = 0.0f, cb = 0.0f;
#pragma unroll
    for (int s = 0; s < 12; s++) {
        if ((pos >> s) & 1) {
            int node = ((LEAF + pos) >> s) - 1;
            float scl = g_scale[s];
            size_t off = (size_t)((node * 2 + b) * 8 + h) * 128;
            int kv = (s == 0) ? 1 : 2;
            for (int k = 0; k < kv; k++) {
                float va = g_tree[off + k * 64 + lane];
                float vb = g_tree[off + k * 64 + lane + 32];
                float ua = g_u[off + k * 64 + lane];
                float ub = g_u[off + k * 64 + lane + 32];
                float dot = wsum(qa * (va + ua) + qb * (vb + ub)) * scl;
                float nm = fmaxf(m, dot);
                float f = __expf(m - nm);
                float e = __expf(dot - nm);
                den = den * f + e;
                ca = ca * f + e * va;
                cb = cb * f + e * vb;
                m = nm;
            }
        }
    }
    float inv = 1.0f / den;
    size_t o = (size_t)(b * LL + t) * DMODEL + h * 64;
    g_ctx[o + lane] = ca * inv;
    g_ctx[o + lane + 32] = cb * inv;
}

// ---------------- launcher ----------------
extern "C" void kernel_launch(void* const* d_in, const int* in_sizes, int n_in,
                              void* d_out, int out_size)
{
    const float* x      = (const float*)d_in[0];
    const float* Wq     = (const float*)d_in[1];
    const float* Wv     = (const float*)d_in[2];
    const float* Wo     = (const float*)d_in[3];
    const float* glw    = (const float*)d_in[4];
    const float* glb    = (const float*)d_in[5];
    const float* grw    = (const float*)d_in[6];
    const float* grb    = (const float*)d_in[7];
    const float* pqb    = (const float*)d_in[8];
    const float* qow    = (const float*)d_in[9];
    const float* qob    = (const float*)d_in[10];
    const float* lng    = (const float*)d_in[11];
    const float* lnb    = (const float*)d_in[12];
    const float* skw    = (const float*)d_in[13];
    const float* salpha = (const float*)d_in[14];
    const float* wfreq  = (const float*)d_in[15];
    const float* wdamp  = (const float*)d_in[16];
    const float* wphase = (const float*)d_in[17];
    const float* dpw    = (const float*)d_in[18];
    const float* dtemp  = (const float*)d_in[19];

    precompute_kernel<<<1, 256>>>(glw, grw, pqb, qow, qob, skw, salpha,
                                  wfreq, wdamp, wphase, dtemp);

    // q_base = x @ Wq^T ; v -> tree leaves = x @ Wv^T   (bf16-split tensor cores)
    gemm_bf16s<2, 0><<<dim3(32, 4), 256>>>(x, Wq, nullptr);
    gemm_bf16s<1, 0><<<dim3(32, 4), 256>>>(x, Wv, nullptr);

    // tree merges, levels 1..11 (root unused by covers)
    for (int d = 1; d <= 11; d++) {
        int lo = 1 << (12 - d);
        if (d == 1) merge_kernel<1><<<lo, 256>>>(d, lo, glb, grb, lng, lnb);
        else        merge_kernel<2><<<lo, 256>>>(d, lo, glb, grb, lng, lnb);
    }

    // u = W_s^T v on cover-reachable nodes (replaces qproj materialization)
    utransform_kernel<<<2048, 256>>>(dpw);

    // cover attention -> ctx
    cover_attn_kernel<<<dim3(LL, BB), 256>>>();

    // out = ctx @ Wo^T
    gemm_bf16s<0, 1><<<dim3(32, 4), 256>>>(nullptr, Wo, (float*)d_out);
}